// round 15
// baseline (speedup 1.0000x reference)
#include <cuda_runtime.h>
#include <cuda_bf16.h>
#include <stdint.h>
#include <math.h>

#define N_ROWS 16384
#define D 128
#define NCLS 10
#define BM 128
#define BN 128
#define NBLK (N_ROWS / BM)       // 128
#define NCTA 296                 // 2 per SM x 148 SMs
#define BASE_T 27                // tiles per CTA (first 264 CTAs get 28)
#define REM_T 264

// exp(5c-5) = 2^(c*K1 - K1), K1 = 5*log2(e)
#define K1 7.2134752044448170f

// ---- static device scratch ----
__device__ __align__(16) __nv_bfloat16  g_featb[N_ROWS * D];
__device__ int   g_lab[N_ROWS];
__device__ float g_S[N_ROWS];
__device__ float g_G[D * NCLS];
__device__ int   g_hist[NCLS];
__device__ int   g_is64;
__device__ float g_part[1024];
__device__ float g_pcnt[1024];

__device__ __forceinline__ uint32_t smem_u32(const void* p) {
    uint32_t a;
    asm("{ .reg .u64 t; cvta.to.shared.u64 t, %1; cvt.u32.u64 %0, t; }" : "=r"(a) : "l"(p));
    return a;
}

// swizzled tile offset: 128 rows x 256B; 16B chunk c at ((c&8)|((c&7)^(row&7)))
__device__ __forceinline__ uint32_t toff(uint32_t row, uint32_t chunk) {
    return row * 256u + (((chunk & 8u) | ((chunk & 7u) ^ (row & 7u))) << 4);
}

#define LDSM4(r, addr)                                                          \
    asm volatile("ldmatrix.sync.aligned.m8n8.x4.shared.b16 {%0,%1,%2,%3}, [%4];"\
        : "=r"((r)[0]), "=r"((r)[1]), "=r"((r)[2]), "=r"((r)[3]) : "r"(addr))

#define MMA16816(c, a, b0, b1)                                                  \
    asm volatile("mma.sync.aligned.m16n8k16.row.col.f32.bf16.bf16.f32 "         \
        "{%0,%1,%2,%3}, {%4,%5,%6,%7}, {%8,%9}, {%0,%1,%2,%3};"                 \
        : "+f"((c)[0]), "+f"((c)[1]), "+f"((c)[2]), "+f"((c)[3])                \
        : "r"((a)[0]), "r"((a)[1]), "r"((a)[2]), "r"((a)[3]), "r"(b0), "r"(b1))

#define CP16(dst, src)                                                          \
    asm volatile("cp.async.cg.shared.global [%0], [%1], 16;" :: "r"(dst), "l"(src))
#define CP_COMMIT() asm volatile("cp.async.commit_group;" ::: "memory")
#define CP_WAIT0()  asm volatile("cp.async.wait_group 0;" ::: "memory")

#define EX2F(e, y) asm("ex2.approx.ftz.f32 %0, %1;" : "=f"(e) : "f"(y))

// ---------------------------------------------------------------------------
__global__ void detect_kernel(const int* __restrict__ lab32) {
    int t = threadIdx.x;                       // 1024
    if (t < D * NCLS) g_G[t] = 0.0f;
    if (t + 1024 < D * NCLS) g_G[t + 1024] = 0.0f;
    if (t < NCLS) g_hist[t] = 0;
    if (t == 0) {
        int any = 0;
        for (int i = 1; i < 64; i += 2) any |= lab32[i];
        g_is64 = (any == 0) ? 1 : 0;
    }
}

// ---------------------------------------------------------------------------
// Prep: 128 blocks x 256 threads, 128 rows/block, 32 lanes per row (float4).
// G + histogram accumulated in SMEM, flushed once per block (164K global
// REDs total instead of 2.1M contended ones).
__global__ void prep_kernel(const float* __restrict__ feat,
                            const void* __restrict__ labp) {
    __shared__ float sG[D * NCLS];             // same layout as g_G: [k][c]
    __shared__ int sHist[NCLS];
    const int tid = threadIdx.x;               // 256
    const int lane = tid & 31;
    const int wid = tid >> 5;
    for (int u = tid; u < D * NCLS; u += 256) sG[u] = 0.0f;
    if (tid < NCLS) sHist[tid] = 0;
    __syncthreads();

    const int row0 = blockIdx.x * 128;
    const int is64 = g_is64;
    #pragma unroll 1
    for (int rp = 0; rp < 16; rp++) {
        const int row = row0 + rp * 8 + wid;
        float4 v = ((const float4*)(feat + (size_t)row * D))[lane];
        float ss = v.x * v.x + v.y * v.y + v.z * v.z + v.w * v.w;
        #pragma unroll
        for (int o = 16; o > 0; o >>= 1) ss += __shfl_xor_sync(0xffffffffu, ss, o);
        const float inv = rsqrtf(ss);
        const float n0 = v.x * inv, n1 = v.y * inv, n2 = v.z * inv, n3 = v.w * inv;

        __nv_bfloat162 b01, b23;
        b01.x = __float2bfloat16(n0); b01.y = __float2bfloat16(n1);
        b23.x = __float2bfloat16(n2); b23.y = __float2bfloat16(n3);
        uint2 pk;
        pk.x = *(uint32_t*)&b01; pk.y = *(uint32_t*)&b23;
        *(uint2*)&g_featb[(size_t)row * D + lane * 4] = pk;

        int lab = 0;
        if (lane == 0) {
            if (is64) lab = (int)((const long long*)labp)[row];
            else      lab = ((const int*)labp)[row];
            g_lab[row] = lab;
            g_S[row] = 0.0f;
            atomicAdd(&sHist[lab], 1);
        }
        lab = __shfl_sync(0xffffffffu, lab, 0);

        const int k = lane * 4;
        atomicAdd(&sG[(k + 0) * NCLS + lab], n0);
        atomicAdd(&sG[(k + 1) * NCLS + lab], n1);
        atomicAdd(&sG[(k + 2) * NCLS + lab], n2);
        atomicAdd(&sG[(k + 3) * NCLS + lab], n3);
    }
    __syncthreads();
    for (int u = tid; u < D * NCLS; u += 256) atomicAdd(&g_G[u], sG[u]);
    if (tid < NCLS) atomicAdd(&g_hist[tid], sHist[tid]);
}

// ---------------------------------------------------------------------------
// Persistent symmetric fused Gram + exp-sum (R11, unchanged). 296 CTAs.
// Tile list bi-major: bi<64 -> d in [0,64]; bi>=64 -> d in [0,63].
extern __shared__ char smem[];

__device__ __forceinline__ void flush_rows(
    float (&accS)[2][2], int i0, int warp_m, int lane, int g)
{
    #pragma unroll
    for (int mi = 0; mi < 2; mi++)
        #pragma unroll
        for (int r = 0; r < 2; r++) {
            float v = accS[mi][r];
            v += __shfl_xor_sync(0xffffffffu, v, 1);
            v += __shfl_xor_sync(0xffffffffu, v, 2);
            if ((lane & 3) == 0)
                atomicAdd(&g_S[i0 + warp_m * 32 + mi * 16 + g + r * 8], v);
            accS[mi][r] = 0.0f;
        }
}

__global__ void __launch_bounds__(256, 2) main_kernel() {
    const uint32_t smem_base = smem_u32(smem);
    const uint32_t smB0 = smem_base + 32768u;
    const int tid = threadIdx.x;
    const int lane = tid & 31;
    const int wid = tid >> 5;
    const int warp_m = wid & 3;
    const int warp_n = wid >> 2;
    const int c = blockIdx.x;

    const int start = (c < REM_T) ? c * (BASE_T + 1)
                                  : REM_T * (BASE_T + 1) + (c - REM_T) * BASE_T;
    const int count = BASE_T + (c < REM_T ? 1 : 0);

    int bi, d;
    if (start < 64 * 65) { bi = start / 65; d = start % 65; }
    else { int u = start - 64 * 65; bi = 64 + u / 64; d = u % 64; }

    {
        const int i0 = bi * BM;
        #pragma unroll
        for (int it = 0; it < 8; it++) {
            int u = tid + it * 256;
            uint32_t row = (uint32_t)u >> 4, ch = (uint32_t)u & 15;
            CP16(smem_base + toff(row, ch),
                 (const void*)&g_featb[(size_t)(i0 + row) * D + ch * 8]);
        }
        const int j0 = ((bi + d) & (NBLK - 1)) * BN;
        #pragma unroll
        for (int it = 0; it < 8; it++) {
            int u = tid + it * 256;
            uint32_t row = (uint32_t)u >> 4, ch = (uint32_t)u & 15;
            CP16(smB0 + toff(row, ch),
                 (const void*)&g_featb[(size_t)(j0 + row) * D + ch * 8]);
        }
        CP_COMMIT();
    }
    int abi = bi;

    const int g = lane >> 2;
    const uint32_t swz = (uint32_t)(lane & 7);
    const uint32_t aBase = smem_base + (uint32_t)(warp_m * 32 + (lane & 15)) * 256u;
    const uint32_t aCh = (uint32_t)(lane >> 4);
    const uint32_t bRowOff = (uint32_t)(warp_n * 64 + (lane & 7) + ((lane >> 4) << 3)) * 256u;
    const uint32_t bCh = (uint32_t)((lane >> 3) & 1);

    float accS[2][2] = {{0.f, 0.f}, {0.f, 0.f}};
    uint32_t p = 0;

    for (int it = 0; it < count; it++) {
        const int j0 = ((bi + d) & (NBLK - 1)) * BN;

        CP_WAIT0();
        if (bi != abi) {
            flush_rows(accS, abi * BM, warp_m, lane, g);
            __syncthreads();
            const int i0 = bi * BM;
            #pragma unroll
            for (int k = 0; k < 8; k++) {
                int u = tid + k * 256;
                uint32_t row = (uint32_t)u >> 4, ch = (uint32_t)u & 15;
                CP16(smem_base + toff(row, ch),
                     (const void*)&g_featb[(size_t)(i0 + row) * D + ch * 8]);
            }
            CP_COMMIT();
            CP_WAIT0();
            abi = bi;
        }
        __syncthreads();

        if (it + 1 < count) {
            int bi2 = bi, d2 = d + 1;
            if (d2 == ((bi2 < 64) ? 65 : 64)) { d2 = 0; bi2++; }
            const int j0n = ((bi2 + d2) & (NBLK - 1)) * BN;
            const uint32_t smBn = smB0 + (p ^ 1u) * 32768u;
            #pragma unroll
            for (int k = 0; k < 8; k++) {
                int u = tid + k * 256;
                uint32_t row = (uint32_t)u >> 4, ch = (uint32_t)u & 15;
                CP16(smBn + toff(row, ch),
                     (const void*)&g_featb[(size_t)(j0n + row) * D + ch * 8]);
            }
            CP_COMMIT();
        }
        const uint32_t smB = smB0 + p * 32768u;

        float acc[2][8][4];
        #pragma unroll
        for (int mi = 0; mi < 2; mi++)
            #pragma unroll
            for (int nt = 0; nt < 8; nt++)
                #pragma unroll
                for (int q = 0; q < 4; q++) acc[mi][nt][q] = 0.0f;

        #pragma unroll
        for (int ks = 0; ks < 8; ks++) {
            uint32_t a[2][4];
            const uint32_t ca = (uint32_t)(ks * 2) + aCh;
            const uint32_t aoff = ((ca & 8u) | ((ca & 7u) ^ swz)) << 4;
            LDSM4(a[0], aBase + aoff);
            LDSM4(a[1], aBase + 4096u + aoff);
            const uint32_t cb = (uint32_t)(ks * 2) + bCh;
            const uint32_t boff = ((cb & 8u) | ((cb & 7u) ^ swz)) << 4;
            #pragma unroll
            for (int np = 0; np < 4; np++) {
                uint32_t b[4];
                LDSM4(b, smB + bRowOff + (uint32_t)(np * 16) * 256u + boff);
                MMA16816(acc[0][np * 2],     a[0], b[0], b[1]);
                MMA16816(acc[1][np * 2],     a[1], b[0], b[1]);
                MMA16816(acc[0][np * 2 + 1], a[0], b[2], b[3]);
                MMA16816(acc[1][np * 2 + 1], a[1], b[2], b[3]);
            }
        }

        const bool doCols = (d != 0);
        #pragma unroll
        for (int nt = 0; nt < 8; nt++) {
            float e[2][4];
            #pragma unroll
            for (int mi = 0; mi < 2; mi++)
                #pragma unroll
                for (int q = 0; q < 4; q++) {
                    float y = fmaf(acc[mi][nt][q], K1, -K1);
                    EX2F(e[mi][q], y);
                }
            #pragma unroll
            for (int mi = 0; mi < 2; mi++) {
                accS[mi][0] += e[mi][0] + e[mi][1];
                accS[mi][1] += e[mi][2] + e[mi][3];
            }
            if (doCols) {
                float c0 = (e[0][0] + e[0][2]) + (e[1][0] + e[1][2]);
                float c1 = (e[0][1] + e[0][3]) + (e[1][1] + e[1][3]);
                c0 += __shfl_xor_sync(0xffffffffu, c0, 4);
                c0 += __shfl_xor_sync(0xffffffffu, c0, 8);
                c0 += __shfl_xor_sync(0xffffffffu, c0, 16);
                c1 += __shfl_xor_sync(0xffffffffu, c1, 4);
                c1 += __shfl_xor_sync(0xffffffffu, c1, 8);
                c1 += __shfl_xor_sync(0xffffffffu, c1, 16);
                if (lane < 4) {
                    atomicAdd(&g_S[j0 + warp_n * 64 + nt * 8 + 2 * lane], c0);
                    atomicAdd(&g_S[j0 + warp_n * 64 + nt * 8 + 2 * lane + 1], c1);
                }
            }
        }

        p ^= 1u;
        d++;
        if (d == ((bi < 64) ? 65 : 64)) { d = 0; bi++; }
    }

    flush_rows(accS, abi * BM, warp_m, lane, g);
}

// ---------------------------------------------------------------------------
// 2 rows per warp, 16 lanes/row, uint4 loads. G transposed in SMEM [c][k].
__global__ void partial_kernel() {
    __shared__ float sGT[NCLS * D];
    __shared__ float sl[8], sv[8];
    const int tid = threadIdx.x;               // 256
    const int lane = tid & 31;
    const int wid = tid >> 5;
    for (int u = tid; u < NCLS * D; u += 256) {
        int cc = u >> 7, k = u & 127;
        sGT[u] = g_G[k * NCLS + cc];
    }
    __syncthreads();

    const int lr = lane & 15;
    const int row = blockIdx.x * 16 + wid * 2 + (lane >> 4);
    const int lab = g_lab[row];
    uint4 pk = *(const uint4*)&g_featb[(size_t)row * D + lr * 8];
    const float* gt = &sGT[lab * D + lr * 8];
    const __nv_bfloat162* pp = (const __nv_bfloat162*)&pk;
    float dd = 0.0f;
    #pragma unroll
    for (int i = 0; i < 4; i++) {
        dd = fmaf(__bfloat162float(pp[i].x), gt[2 * i], dd);
        dd = fmaf(__bfloat162float(pp[i].y), gt[2 * i + 1], dd);
    }
    #pragma unroll
    for (int o = 1; o < 16; o <<= 1) dd += __shfl_xor_sync(0xffffffffu, dd, o);

    float ls = 0.0f, vv = 0.0f;
    if (lr == 0) {
        const float C = (float)(g_hist[lab] - 1);
        if (C > 0.5f) {
            float P = 5.0f * dd - 5.0f;
            ls = 0.2f * (5.0f + logf(g_S[row] - 1.0f) - P / C);
            vv = 1.0f;
        }
    }
    ls += __shfl_down_sync(0xffffffffu, ls, 16);
    vv += __shfl_down_sync(0xffffffffu, vv, 16);
    if (lane == 0) { sl[wid] = ls; sv[wid] = vv; }
    __syncthreads();
    if (tid == 0) {
        float L = 0.f, V = 0.f;
        #pragma unroll
        for (int w = 0; w < 8; w++) { L += sl[w]; V += sv[w]; }
        g_part[blockIdx.x] = L;
        g_pcnt[blockIdx.x] = V;
    }
}

__global__ void final_kernel(float* __restrict__ out) {
    const int t = threadIdx.x;   // 1024
    float l = g_part[t];
    float v = g_pcnt[t];
    #pragma unroll
    for (int o = 16; o > 0; o >>= 1) {
        l += __shfl_down_sync(0xffffffffu, l, o);
        v += __shfl_down_sync(0xffffffffu, v, o);
    }
    __shared__ float a[32], b[32];
    if ((t & 31) == 0) { a[t >> 5] = l; b[t >> 5] = v; }
    __syncthreads();
    if (t < 32) {
        float L = a[t], V = b[t];
        #pragma unroll
        for (int o = 16; o > 0; o >>= 1) {
            L += __shfl_down_sync(0xffffffffu, L, o);
            V += __shfl_down_sync(0xffffffffu, V, o);
        }
        if (t == 0) out[0] = L / fmaxf(V, 1.0f);
    }
}

// ---------------------------------------------------------------------------
extern "C" void kernel_launch(void* const* d_in, const int* in_sizes, int n_in,
                              void* d_out, int out_size) {
    const float* feat = (const float*)d_in[0];
    const void*  labp = d_in[1];
    float* out = (float*)d_out;

    const int smem_bytes = 3 * 32768;
    cudaFuncSetAttribute(main_kernel, cudaFuncAttributeMaxDynamicSharedMemorySize,
                         smem_bytes);

    detect_kernel<<<1, 1024>>>((const int*)labp);
    prep_kernel<<<128, 256>>>(feat, labp);
    main_kernel<<<NCTA, 256, smem_bytes>>>();
    partial_kernel<<<1024, 256>>>();
    final_kernel<<<1, 1024>>>(out);
}

// round 16
// speedup vs baseline: 1.0153x; 1.0153x over previous
#include <cuda_runtime.h>
#include <cuda_bf16.h>
#include <stdint.h>
#include <math.h>

#define N_ROWS 16384
#define D 128
#define NCLS 10
#define BM 128
#define BN 128
#define NBLK (N_ROWS / BM)       // 128
#define NCTA 296                 // 2 per SM x 148 SMs
#define BASE_T 27                // tiles per CTA (first 264 CTAs get 28)
#define REM_T 264

// exp(5c-5) = 2^(c*K1 - K1), K1 = 5*log2(e)
#define K1 7.2134752044448170f

// ---- static device scratch ----
__device__ __align__(16) __nv_bfloat16  g_featb[N_ROWS * D];
__device__ int   g_lab[N_ROWS];
__device__ float g_S[N_ROWS];
__device__ float g_G[D * NCLS];
__device__ int   g_hist[NCLS];
__device__ int   g_is64;
__device__ float g_part[1024];
__device__ float g_pcnt[1024];

__device__ __forceinline__ uint32_t smem_u32(const void* p) {
    uint32_t a;
    asm("{ .reg .u64 t; cvta.to.shared.u64 t, %1; cvt.u32.u64 %0, t; }" : "=r"(a) : "l"(p));
    return a;
}

// swizzled tile offset: 128 rows x 256B; 16B chunk c at ((c&8)|((c&7)^(row&7)))
__device__ __forceinline__ uint32_t toff(uint32_t row, uint32_t chunk) {
    return row * 256u + (((chunk & 8u) | ((chunk & 7u) ^ (row & 7u))) << 4);
}

#define LDSM4(r, addr)                                                          \
    asm volatile("ldmatrix.sync.aligned.m8n8.x4.shared.b16 {%0,%1,%2,%3}, [%4];"\
        : "=r"((r)[0]), "=r"((r)[1]), "=r"((r)[2]), "=r"((r)[3]) : "r"(addr))

#define MMA16816(c, a, b0, b1)                                                  \
    asm volatile("mma.sync.aligned.m16n8k16.row.col.f32.bf16.bf16.f32 "         \
        "{%0,%1,%2,%3}, {%4,%5,%6,%7}, {%8,%9}, {%0,%1,%2,%3};"                 \
        : "+f"((c)[0]), "+f"((c)[1]), "+f"((c)[2]), "+f"((c)[3])                \
        : "r"((a)[0]), "r"((a)[1]), "r"((a)[2]), "r"((a)[3]), "r"(b0), "r"(b1))

#define CP16(dst, src)                                                          \
    asm volatile("cp.async.cg.shared.global [%0], [%1], 16;" :: "r"(dst), "l"(src))
#define CP_COMMIT() asm volatile("cp.async.commit_group;" ::: "memory")
#define CP_WAIT0()  asm volatile("cp.async.wait_group 0;" ::: "memory")

#define EX2F(e, y) asm("ex2.approx.ftz.f32 %0, %1;" : "=f"(e) : "f"(y))

// ---------------------------------------------------------------------------
__global__ void detect_kernel(const int* __restrict__ lab32) {
    int t = threadIdx.x;                       // 1024
    if (t < D * NCLS) g_G[t] = 0.0f;
    if (t + 1024 < D * NCLS) g_G[t + 1024] = 0.0f;
    if (t < NCLS) g_hist[t] = 0;
    if (t == 0) {
        int any = 0;
        for (int i = 1; i < 64; i += 2) any |= lab32[i];
        g_is64 = (any == 0) ? 1 : 0;
    }
}

// ---------------------------------------------------------------------------
// Prep: 128 blocks x 256 threads, 128 rows/block, 32 lanes per row (float4).
// G + histogram accumulated in SMEM, flushed once per block (164K global
// REDs total instead of 2.1M contended ones).
__global__ void prep_kernel(const float* __restrict__ feat,
                            const void* __restrict__ labp) {
    __shared__ float sG[D * NCLS];             // same layout as g_G: [k][c]
    __shared__ int sHist[NCLS];
    const int tid = threadIdx.x;               // 256
    const int lane = tid & 31;
    const int wid = tid >> 5;
    for (int u = tid; u < D * NCLS; u += 256) sG[u] = 0.0f;
    if (tid < NCLS) sHist[tid] = 0;
    __syncthreads();

    const int row0 = blockIdx.x * 128;
    const int is64 = g_is64;
    #pragma unroll 1
    for (int rp = 0; rp < 16; rp++) {
        const int row = row0 + rp * 8 + wid;
        float4 v = ((const float4*)(feat + (size_t)row * D))[lane];
        float ss = v.x * v.x + v.y * v.y + v.z * v.z + v.w * v.w;
        #pragma unroll
        for (int o = 16; o > 0; o >>= 1) ss += __shfl_xor_sync(0xffffffffu, ss, o);
        const float inv = rsqrtf(ss);
        const float n0 = v.x * inv, n1 = v.y * inv, n2 = v.z * inv, n3 = v.w * inv;

        __nv_bfloat162 b01, b23;
        b01.x = __float2bfloat16(n0); b01.y = __float2bfloat16(n1);
        b23.x = __float2bfloat16(n2); b23.y = __float2bfloat16(n3);
        uint2 pk;
        pk.x = *(uint32_t*)&b01; pk.y = *(uint32_t*)&b23;
        *(uint2*)&g_featb[(size_t)row * D + lane * 4] = pk;

        int lab = 0;
        if (lane == 0) {
            if (is64) lab = (int)((const long long*)labp)[row];
            else      lab = ((const int*)labp)[row];
            g_lab[row] = lab;
            g_S[row] = 0.0f;
            atomicAdd(&sHist[lab], 1);
        }
        lab = __shfl_sync(0xffffffffu, lab, 0);

        const int k = lane * 4;
        atomicAdd(&sG[(k + 0) * NCLS + lab], n0);
        atomicAdd(&sG[(k + 1) * NCLS + lab], n1);
        atomicAdd(&sG[(k + 2) * NCLS + lab], n2);
        atomicAdd(&sG[(k + 3) * NCLS + lab], n3);
    }
    __syncthreads();
    for (int u = tid; u < D * NCLS; u += 256) atomicAdd(&g_G[u], sG[u]);
    if (tid < NCLS) atomicAdd(&g_hist[tid], sHist[tid]);
}

// ---------------------------------------------------------------------------
// Persistent symmetric fused Gram + exp-sum (R11, unchanged). 296 CTAs.
// Tile list bi-major: bi<64 -> d in [0,64]; bi>=64 -> d in [0,63].
extern __shared__ char smem[];

__device__ __forceinline__ void flush_rows(
    float (&accS)[2][2], int i0, int warp_m, int lane, int g)
{
    #pragma unroll
    for (int mi = 0; mi < 2; mi++)
        #pragma unroll
        for (int r = 0; r < 2; r++) {
            float v = accS[mi][r];
            v += __shfl_xor_sync(0xffffffffu, v, 1);
            v += __shfl_xor_sync(0xffffffffu, v, 2);
            if ((lane & 3) == 0)
                atomicAdd(&g_S[i0 + warp_m * 32 + mi * 16 + g + r * 8], v);
            accS[mi][r] = 0.0f;
        }
}

__global__ void __launch_bounds__(256, 2) main_kernel() {
    const uint32_t smem_base = smem_u32(smem);
    const uint32_t smB0 = smem_base + 32768u;
    const int tid = threadIdx.x;
    const int lane = tid & 31;
    const int wid = tid >> 5;
    const int warp_m = wid & 3;
    const int warp_n = wid >> 2;
    const int c = blockIdx.x;

    const int start = (c < REM_T) ? c * (BASE_T + 1)
                                  : REM_T * (BASE_T + 1) + (c - REM_T) * BASE_T;
    const int count = BASE_T + (c < REM_T ? 1 : 0);

    int bi, d;
    if (start < 64 * 65) { bi = start / 65; d = start % 65; }
    else { int u = start - 64 * 65; bi = 64 + u / 64; d = u % 64; }

    {
        const int i0 = bi * BM;
        #pragma unroll
        for (int it = 0; it < 8; it++) {
            int u = tid + it * 256;
            uint32_t row = (uint32_t)u >> 4, ch = (uint32_t)u & 15;
            CP16(smem_base + toff(row, ch),
                 (const void*)&g_featb[(size_t)(i0 + row) * D + ch * 8]);
        }
        const int j0 = ((bi + d) & (NBLK - 1)) * BN;
        #pragma unroll
        for (int it = 0; it < 8; it++) {
            int u = tid + it * 256;
            uint32_t row = (uint32_t)u >> 4, ch = (uint32_t)u & 15;
            CP16(smB0 + toff(row, ch),
                 (const void*)&g_featb[(size_t)(j0 + row) * D + ch * 8]);
        }
        CP_COMMIT();
    }
    int abi = bi;

    const int g = lane >> 2;
    const uint32_t swz = (uint32_t)(lane & 7);
    const uint32_t aBase = smem_base + (uint32_t)(warp_m * 32 + (lane & 15)) * 256u;
    const uint32_t aCh = (uint32_t)(lane >> 4);
    const uint32_t bRowOff = (uint32_t)(warp_n * 64 + (lane & 7) + ((lane >> 4) << 3)) * 256u;
    const uint32_t bCh = (uint32_t)((lane >> 3) & 1);

    float accS[2][2] = {{0.f, 0.f}, {0.f, 0.f}};
    uint32_t p = 0;

    for (int it = 0; it < count; it++) {
        const int j0 = ((bi + d) & (NBLK - 1)) * BN;

        CP_WAIT0();
        if (bi != abi) {
            flush_rows(accS, abi * BM, warp_m, lane, g);
            __syncthreads();
            const int i0 = bi * BM;
            #pragma unroll
            for (int k = 0; k < 8; k++) {
                int u = tid + k * 256;
                uint32_t row = (uint32_t)u >> 4, ch = (uint32_t)u & 15;
                CP16(smem_base + toff(row, ch),
                     (const void*)&g_featb[(size_t)(i0 + row) * D + ch * 8]);
            }
            CP_COMMIT();
            CP_WAIT0();
            abi = bi;
        }
        __syncthreads();

        if (it + 1 < count) {
            int bi2 = bi, d2 = d + 1;
            if (d2 == ((bi2 < 64) ? 65 : 64)) { d2 = 0; bi2++; }
            const int j0n = ((bi2 + d2) & (NBLK - 1)) * BN;
            const uint32_t smBn = smB0 + (p ^ 1u) * 32768u;
            #pragma unroll
            for (int k = 0; k < 8; k++) {
                int u = tid + k * 256;
                uint32_t row = (uint32_t)u >> 4, ch = (uint32_t)u & 15;
                CP16(smBn + toff(row, ch),
                     (const void*)&g_featb[(size_t)(j0n + row) * D + ch * 8]);
            }
            CP_COMMIT();
        }
        const uint32_t smB = smB0 + p * 32768u;

        float acc[2][8][4];
        #pragma unroll
        for (int mi = 0; mi < 2; mi++)
            #pragma unroll
            for (int nt = 0; nt < 8; nt++)
                #pragma unroll
                for (int q = 0; q < 4; q++) acc[mi][nt][q] = 0.0f;

        #pragma unroll
        for (int ks = 0; ks < 8; ks++) {
            uint32_t a[2][4];
            const uint32_t ca = (uint32_t)(ks * 2) + aCh;
            const uint32_t aoff = ((ca & 8u) | ((ca & 7u) ^ swz)) << 4;
            LDSM4(a[0], aBase + aoff);
            LDSM4(a[1], aBase + 4096u + aoff);
            const uint32_t cb = (uint32_t)(ks * 2) + bCh;
            const uint32_t boff = ((cb & 8u) | ((cb & 7u) ^ swz)) << 4;
            #pragma unroll
            for (int np = 0; np < 4; np++) {
                uint32_t b[4];
                LDSM4(b, smB + bRowOff + (uint32_t)(np * 16) * 256u + boff);
                MMA16816(acc[0][np * 2],     a[0], b[0], b[1]);
                MMA16816(acc[1][np * 2],     a[1], b[0], b[1]);
                MMA16816(acc[0][np * 2 + 1], a[0], b[2], b[3]);
                MMA16816(acc[1][np * 2 + 1], a[1], b[2], b[3]);
            }
        }

        const bool doCols = (d != 0);
        #pragma unroll
        for (int nt = 0; nt < 8; nt++) {
            float e[2][4];
            #pragma unroll
            for (int mi = 0; mi < 2; mi++)
                #pragma unroll
                for (int q = 0; q < 4; q++) {
                    float y = fmaf(acc[mi][nt][q], K1, -K1);
                    EX2F(e[mi][q], y);
                }
            #pragma unroll
            for (int mi = 0; mi < 2; mi++) {
                accS[mi][0] += e[mi][0] + e[mi][1];
                accS[mi][1] += e[mi][2] + e[mi][3];
            }
            if (doCols) {
                float c0 = (e[0][0] + e[0][2]) + (e[1][0] + e[1][2]);
                float c1 = (e[0][1] + e[0][3]) + (e[1][1] + e[1][3]);
                c0 += __shfl_xor_sync(0xffffffffu, c0, 4);
                c0 += __shfl_xor_sync(0xffffffffu, c0, 8);
                c0 += __shfl_xor_sync(0xffffffffu, c0, 16);
                c1 += __shfl_xor_sync(0xffffffffu, c1, 4);
                c1 += __shfl_xor_sync(0xffffffffu, c1, 8);
                c1 += __shfl_xor_sync(0xffffffffu, c1, 16);
                if (lane < 4) {
                    atomicAdd(&g_S[j0 + warp_n * 64 + nt * 8 + 2 * lane], c0);
                    atomicAdd(&g_S[j0 + warp_n * 64 + nt * 8 + 2 * lane + 1], c1);
                }
            }
        }

        p ^= 1u;
        d++;
        if (d == ((bi < 64) ? 65 : 64)) { d = 0; bi++; }
    }

    flush_rows(accS, abi * BM, warp_m, lane, g);
}

// ---------------------------------------------------------------------------
// 2 rows per warp, 16 lanes/row, uint4 loads. G transposed in SMEM [c][k].
__global__ void partial_kernel() {
    __shared__ float sGT[NCLS * D];
    __shared__ float sl[8], sv[8];
    const int tid = threadIdx.x;               // 256
    const int lane = tid & 31;
    const int wid = tid >> 5;
    for (int u = tid; u < NCLS * D; u += 256) {
        int cc = u >> 7, k = u & 127;
        sGT[u] = g_G[k * NCLS + cc];
    }
    __syncthreads();

    const int lr = lane & 15;
    const int row = blockIdx.x * 16 + wid * 2 + (lane >> 4);
    const int lab = g_lab[row];
    uint4 pk = *(const uint4*)&g_featb[(size_t)row * D + lr * 8];
    const float* gt = &sGT[lab * D + lr * 8];
    const __nv_bfloat162* pp = (const __nv_bfloat162*)&pk;
    float dd = 0.0f;
    #pragma unroll
    for (int i = 0; i < 4; i++) {
        dd = fmaf(__bfloat162float(pp[i].x), gt[2 * i], dd);
        dd = fmaf(__bfloat162float(pp[i].y), gt[2 * i + 1], dd);
    }
    #pragma unroll
    for (int o = 1; o < 16; o <<= 1) dd += __shfl_xor_sync(0xffffffffu, dd, o);

    float ls = 0.0f, vv = 0.0f;
    if (lr == 0) {
        const float C = (float)(g_hist[lab] - 1);
        if (C > 0.5f) {
            float P = 5.0f * dd - 5.0f;
            ls = 0.2f * (5.0f + logf(g_S[row] - 1.0f) - P / C);
            vv = 1.0f;
        }
    }
    ls += __shfl_down_sync(0xffffffffu, ls, 16);
    vv += __shfl_down_sync(0xffffffffu, vv, 16);
    if (lane == 0) { sl[wid] = ls; sv[wid] = vv; }
    __syncthreads();
    if (tid == 0) {
        float L = 0.f, V = 0.f;
        #pragma unroll
        for (int w = 0; w < 8; w++) { L += sl[w]; V += sv[w]; }
        g_part[blockIdx.x] = L;
        g_pcnt[blockIdx.x] = V;
    }
}

__global__ void final_kernel(float* __restrict__ out) {
    const int t = threadIdx.x;   // 1024
    float l = g_part[t];
    float v = g_pcnt[t];
    #pragma unroll
    for (int o = 16; o > 0; o >>= 1) {
        l += __shfl_down_sync(0xffffffffu, l, o);
        v += __shfl_down_sync(0xffffffffu, v, o);
    }
    __shared__ float a[32], b[32];
    if ((t & 31) == 0) { a[t >> 5] = l; b[t >> 5] = v; }
    __syncthreads();
    if (t < 32) {
        float L = a[t], V = b[t];
        #pragma unroll
        for (int o = 16; o > 0; o >>= 1) {
            L += __shfl_down_sync(0xffffffffu, L, o);
            V += __shfl_down_sync(0xffffffffu, V, o);
        }
        if (t == 0) out[0] = L / fmaxf(V, 1.0f);
    }
}

// ---------------------------------------------------------------------------
extern "C" void kernel_launch(void* const* d_in, const int* in_sizes, int n_in,
                              void* d_out, int out_size) {
    const float* feat = (const float*)d_in[0];
    const void*  labp = d_in[1];
    float* out = (float*)d_out;

    const int smem_bytes = 3 * 32768;
    cudaFuncSetAttribute(main_kernel, cudaFuncAttributeMaxDynamicSharedMemorySize,
                         smem_bytes);

    detect_kernel<<<1, 1024>>>((const int*)labp);
    prep_kernel<<<128, 256>>>(feat, labp);
    main_kernel<<<NCTA, 256, smem_bytes>>>();
    partial_kernel<<<1024, 256>>>();
    final_kernel<<<1, 1024>>>(out);
}